// round 2
// baseline (speedup 1.0000x reference)
#include <cuda_runtime.h>
#include <cstdint>
#include <math.h>

#define B_ 8
#define S_ 256
#define V_ 50257
#define D_ 128
#define N_ 256
#define L_ 2
#define M_ (B_*S_)   // 2048

__device__ float g_X[M_*D_];   // activation rows, layout row = t*B + b
__device__ float g_sin[4096];
__device__ float g_cos[4096];

__device__ __forceinline__ unsigned f2tf(float f){
    unsigned u; asm("cvt.rna.tf32.f32 %0, %1;" : "=r"(u) : "f"(f)); return u;
}

__constant__ float PHI_F   = 1.6180339887498949f;
__constant__ float SCALE_F = 651.8986469044033f;     // RES / (2*pi)
__constant__ float STEP_F  = 0.0015339807878856412f; // (2*pi) / RES

// ---------------------------------------------------------------------------
// K0: build sin/cos tables exactly like the reference:
// angles = (float)i * (f32)(2pi/4096); sinf/cosf = libdevice __nv_sinf/__nv_cosf,
// the same functions XLA lowers jnp.sin / jnp.cos to on GPU.
// ---------------------------------------------------------------------------
__global__ void tab_kernel()
{
    int i = blockIdx.x * 256 + threadIdx.x;
    float a = __fmul_rn((float)i, STEP_F);
    g_sin[i] = sinf(a);
    g_cos[i] = cosf(a);
}

// theta -> table index, bit-matching jnp.round(theta*SCALE).astype(int32) % 4096
__device__ __forceinline__ int theta_idx(float theta)
{
    return __float2int_rn(__fmul_rn(theta, SCALE_F)) & 4095;
}

// ---------------------------------------------------------------------------
// K1: sequential scan over t (elementwise in (b,d)). All arithmetic uses
// explicit round-to-nearest intrinsics so nvcc cannot fuse FMAs -- the scan
// trajectory must match XLA bit-for-bit (index flips decorrelate h).
// ---------------------------------------------------------------------------
__global__ void scan_kernel(const int* __restrict__ ids,
                            const float* __restrict__ emb,
                            float* __restrict__ out)
{
    int b = blockIdx.x;
    int d = threadIdx.x;
    float hr = 0.f, hi = 0.f;

    // prefetch t=0
    int id0 = ids[b*S_];
    float w  = __ldg(&emb[(size_t)id0*(2*D_) + d]);
    float bb = __ldg(&emb[(size_t)id0*(2*D_) + D_ + d]);

    for (int t = 0; t < S_; ++t) {
        float w_c = w, bb_c = bb;
        if (t + 1 < S_) {                       // prefetch next step (indep of h)
            int id = ids[b*S_ + t + 1];
            w  = __ldg(&emb[(size_t)id*(2*D_) + d]);
            bb = __ldg(&emb[(size_t)id*(2*D_) + D_ + d]);
        }
        float tphi  = __fmul_rn((float)t, PHI_F);
        float num   = __fadd_rn(hr, hi);
        float den   = __fadd_rn(1.0f, fabsf(w_c));
        float theta = __fadd_rn(__fadd_rn(__fdiv_rn(num, den), bb_c), tphi);
        int idx = theta_idx(theta);
        hi = __ldg(&g_sin[idx]);
        hr = __ldg(&g_cos[idx]);
        g_X[(t*B_ + b)*D_ + d] = __fadd_rn(hr, hi);
    }
    size_t tail = (size_t)B_ * S_ * V_;
    out[tail + b*D_ + d]         = hr;
    out[tail + B_*D_ + b*D_ + d] = hi;
}

// ---------------------------------------------------------------------------
// K2: 2 MLP layers, parallel over all 2048 rows. 8 rows per block.
// ---------------------------------------------------------------------------
#define R_ 8
__global__ __launch_bounds__(256)
void layers_kernel(const float* __restrict__ W,
                   const float* __restrict__ bvec,
                   const float* __restrict__ Wr,
                   const float* __restrict__ Wi)
{
    __shared__ float xs[R_][D_];
    __shared__ float cs[R_][N_];
    __shared__ float sn[R_][N_];
    __shared__ float po[R_][N_];

    int tid = threadIdx.x;
    int g0  = blockIdx.x * R_;

    for (int idx = tid; idx < R_*D_; idx += 256)
        xs[idx >> 7][idx & 127] = g_X[g0*D_ + idx];

    float tphi[R_];
#pragma unroll
    for (int r = 0; r < R_; ++r)
        tphi[r] = __fmul_rn((float)((g0 + r) >> 3), PHI_F);   // t = row / B
    __syncthreads();

    for (int l = 0; l < L_; ++l) {
        // ---- phase A: th = x @ W.T + b + t_phi ; table lookup ----
        {
            int n = tid;
            const float* wrow = W + ((size_t)l*N_ + n)*D_;
            float acc[R_];
#pragma unroll
            for (int r = 0; r < R_; ++r) acc[r] = 0.f;
            for (int d = 0; d < D_; ++d) {
                float w = wrow[d];
#pragma unroll
                for (int r = 0; r < R_; ++r) acc[r] += xs[r][d] * w;
            }
            float bv = bvec[l*N_ + n];
#pragma unroll
            for (int r = 0; r < R_; ++r) {
                float th = __fadd_rn(__fadd_rn(acc[r], bv), tphi[r]);
                int idx = theta_idx(th);
                cs[r][n] = __ldg(&g_cos[idx]);
                sn[r][n] = __ldg(&g_sin[idx]);
            }
        }
        __syncthreads();
        // ---- phase B: o = cs @ Wr.T + sn @ Wi.T (n-range halved) ----
        {
            int half = tid >> 7, d = tid & 127;
            const float* wrrow = Wr + ((size_t)l*D_ + d)*N_;
            const float* wirow = Wi + ((size_t)l*D_ + d)*N_;
            float acc[R_];
#pragma unroll
            for (int r = 0; r < R_; ++r) acc[r] = 0.f;
            int nbeg = half * 128;
            for (int n = nbeg; n < nbeg + 128; ++n) {
                float wr = wrrow[n], wi = wirow[n];
#pragma unroll
                for (int r = 0; r < R_; ++r)
                    acc[r] += cs[r][n]*wr + sn[r][n]*wi;
            }
#pragma unroll
            for (int r = 0; r < R_; ++r) po[r][tid] = acc[r];
        }
        __syncthreads();
        if (tid < 128) {
            int d = tid;
#pragma unroll
            for (int r = 0; r < R_; ++r) {
                float o  = po[r][d] + po[r][128 + d];
                float sg = 1.0f / (1.0f + expf(-o));
                xs[r][d] += o * sg;
            }
        }
        __syncthreads();
    }

    for (int idx = tid; idx < R_*D_; idx += 256)
        g_X[g0*D_ + idx] = xs[idx >> 7][idx & 127];
}

// ---------------------------------------------------------------------------
// K3: logits = X(2048x128) @ out_w^T(128x50257), tf32 mma.sync.m16n8k8.
// BM=BN=128, BK=32. 8 warps: 2(m) x 4(n), each 64x32.
// ---------------------------------------------------------------------------
#define BM 128
#define BN 128
#define BK 32
#define KPAD 4

__global__ __launch_bounds__(256)
void gemm_kernel(const float* __restrict__ Wv, float* __restrict__ out)
{
    __shared__ unsigned As[BM][BK + KPAD];
    __shared__ unsigned Bs[BN][BK + KPAD];

    int tid  = threadIdx.x;
    int lane = tid & 31, warp = tid >> 5;
    int wm = warp >> 2, wn = warp & 3;
    int m0 = blockIdx.x * BM;
    int v0 = blockIdx.y * BN;

    float c[4][4][4];
#pragma unroll
    for (int mt = 0; mt < 4; ++mt)
#pragma unroll
        for (int nt = 0; nt < 4; ++nt)
#pragma unroll
            for (int i = 0; i < 4; ++i) c[mt][nt][i] = 0.f;

    for (int kc = 0; kc < 4; ++kc) {
#pragma unroll
        for (int l = 0; l < 4; ++l) {
            int idx = tid + l*256;
            int row = idx >> 3, c4 = (idx & 7) * 4;
            const float4 v = *reinterpret_cast<const float4*>(
                g_X + (size_t)(m0 + row)*D_ + kc*BK + c4);
            As[row][c4+0] = f2tf(v.x); As[row][c4+1] = f2tf(v.y);
            As[row][c4+2] = f2tf(v.z); As[row][c4+3] = f2tf(v.w);
        }
#pragma unroll
        for (int l = 0; l < 4; ++l) {
            int idx = tid + l*256;
            int row = idx >> 3, c4 = (idx & 7) * 4;
            int gr = v0 + row;
            float4 v = make_float4(0.f, 0.f, 0.f, 0.f);
            if (gr < V_)
                v = *reinterpret_cast<const float4*>(
                    Wv + (size_t)gr*D_ + kc*BK + c4);
            Bs[row][c4+0] = f2tf(v.x); Bs[row][c4+1] = f2tf(v.y);
            Bs[row][c4+2] = f2tf(v.z); Bs[row][c4+3] = f2tf(v.w);
        }
        __syncthreads();

        int ar = lane >> 2, ac = lane & 3;
#pragma unroll
        for (int kk = 0; kk < 4; ++kk) {
            unsigned af[4][4], bf[4][2];
#pragma unroll
            for (int mt = 0; mt < 4; ++mt) {
                int R = wm*64 + mt*16 + ar;
                af[mt][0] = As[R    ][kk*8 + ac    ];
                af[mt][1] = As[R + 8][kk*8 + ac    ];
                af[mt][2] = As[R    ][kk*8 + ac + 4];
                af[mt][3] = As[R + 8][kk*8 + ac + 4];
            }
#pragma unroll
            for (int nt = 0; nt < 4; ++nt) {
                int Rb = wn*32 + nt*8 + ar;
                bf[nt][0] = Bs[Rb][kk*8 + ac    ];
                bf[nt][1] = Bs[Rb][kk*8 + ac + 4];
            }
#pragma unroll
            for (int mt = 0; mt < 4; ++mt)
#pragma unroll
                for (int nt = 0; nt < 4; ++nt) {
                    asm volatile(
                        "mma.sync.aligned.m16n8k8.row.col.f32.tf32.tf32.f32 "
                        "{%0,%1,%2,%3},{%4,%5,%6,%7},{%8,%9},{%0,%1,%2,%3};"
                        : "+f"(c[mt][nt][0]), "+f"(c[mt][nt][1]),
                          "+f"(c[mt][nt][2]), "+f"(c[mt][nt][3])
                        : "r"(af[mt][0]), "r"(af[mt][1]),
                          "r"(af[mt][2]), "r"(af[mt][3]),
                          "r"(bf[nt][0]), "r"(bf[nt][1]));
                }
        }
        __syncthreads();
    }

    // epilogue: row R -> (b = R&7, t = R>>3), out layout (B,S,V)
#pragma unroll
    for (int mt = 0; mt < 4; ++mt) {
        int R0 = m0 + wm*64 + mt*16 + (lane >> 2);
        int R1 = R0 + 8;
        size_t base0 = ((size_t)((R0 & 7)*S_ + (R0 >> 3))) * V_;
        size_t base1 = ((size_t)((R1 & 7)*S_ + (R1 >> 3))) * V_;
#pragma unroll
        for (int nt = 0; nt < 4; ++nt) {
            int col = v0 + wn*32 + nt*8 + (lane & 3)*2;
            if (col < V_) {
                out[base0 + col] = c[mt][nt][0];
                out[base1 + col] = c[mt][nt][2];
            }
            if (col + 1 < V_) {
                out[base0 + col + 1] = c[mt][nt][1];
                out[base1 + col + 1] = c[mt][nt][3];
            }
        }
    }
}

// ---------------------------------------------------------------------------
extern "C" void kernel_launch(void* const* d_in, const int* in_sizes, int n_in,
                              void* d_out, int out_size)
{
    const int*   ids = (const int*)  d_in[0];
    const float* emb = (const float*)d_in[1];
    const float* W   = (const float*)d_in[2];
    const float* bv  = (const float*)d_in[3];
    const float* Wr  = (const float*)d_in[4];
    const float* Wi  = (const float*)d_in[5];
    const float* ow  = (const float*)d_in[6];
    float* out = (float*)d_out;

    tab_kernel<<<16, 256>>>();
    scan_kernel<<<B_, D_>>>(ids, emb, out);
    layers_kernel<<<M_ / R_, 256>>>(W, bv, Wr, Wi);
    dim3 grid(M_ / BM, (V_ + BN - 1) / BN);   // (16, 393), x fastest -> W-tile reuse
    gemm_kernel<<<grid, 256>>>(ow, out);
}

// round 3
// speedup vs baseline: 1.1117x; 1.1117x over previous
#include <cuda_runtime.h>
#include <cstdint>
#include <math.h>

#define B_ 8
#define S_ 256
#define V_ 50257
#define D_ 128
#define N_ 256
#define L_ 2
#define M_ 2048

__device__ float g_X[M_*D_];   // activation rows, row = t*B + b
__device__ float g_sin[4096];
__device__ float g_cos[4096];

__constant__ float PHI_F   = 1.6180339887498949f;
__constant__ float SCALE_F = 651.8986469044033f;     // RES / (2*pi)
__constant__ float STEP_F  = 0.0015339807878856412f; // (2*pi) / RES

__device__ __forceinline__ unsigned f2tf(float f){
    unsigned u; asm("cvt.rna.tf32.f32 %0, %1;" : "=r"(u) : "f"(f)); return u;
}
__device__ __forceinline__ int theta_idx(float theta){
    return __float2int_rn(__fmul_rn(theta, SCALE_F)) & 4095;
}

// ---------------------------------------------------------------------------
// K0: global sin/cos tables (used by layers_kernel)
// ---------------------------------------------------------------------------
__global__ void tab_kernel()
{
    int i = blockIdx.x * 256 + threadIdx.x;
    float a = __fmul_rn((float)i, STEP_F);
    g_sin[i] = sinf(a);
    g_cos[i] = cosf(a);
}

// ---------------------------------------------------------------------------
// K1: sequential scan; bit-exact intrinsics; table lives in smem (29cyc LDS
// on the dependent chain instead of cold-L2 hits).
// ---------------------------------------------------------------------------
__global__ void scan_kernel(const int* __restrict__ ids,
                            const float* __restrict__ emb,
                            float* __restrict__ out)
{
    __shared__ float ssin[4096];
    __shared__ float scos[4096];
    int b = blockIdx.x;
    int d = threadIdx.x;

    for (int i = d; i < 4096; i += 128) {
        float a = __fmul_rn((float)i, STEP_F);
        ssin[i] = sinf(a);
        scos[i] = cosf(a);
    }
    __syncthreads();

    float hr = 0.f, hi = 0.f;
    int id0 = ids[b*S_];
    float w  = __ldg(&emb[(size_t)id0*(2*D_) + d]);
    float bb = __ldg(&emb[(size_t)id0*(2*D_) + D_ + d]);

    for (int t = 0; t < S_; ++t) {
        float w_c = w, bb_c = bb;
        if (t + 1 < S_) {                       // prefetch next step
            int id = ids[b*S_ + t + 1];
            w  = __ldg(&emb[(size_t)id*(2*D_) + d]);
            bb = __ldg(&emb[(size_t)id*(2*D_) + D_ + d]);
        }
        float tphi  = __fmul_rn((float)t, PHI_F);
        float num   = __fadd_rn(hr, hi);
        float den   = __fadd_rn(1.0f, fabsf(w_c));
        float theta = __fadd_rn(__fadd_rn(__fdiv_rn(num, den), bb_c), tphi);
        int idx = theta_idx(theta);
        hi = ssin[idx];
        hr = scos[idx];
        g_X[(t*B_ + b)*D_ + d] = __fadd_rn(hr, hi);
    }
    size_t tail = (size_t)B_ * S_ * V_;
    out[tail + b*D_ + d]         = hr;
    out[tail + B_*D_ + b*D_ + d] = hi;
}

// ---------------------------------------------------------------------------
// K2: 2 MLP layers, 8 rows/block (all 8 rows share t = blockIdx), 256 thr.
// Phase A: thread=n, float4 everywhere. Phase B: Wr/Wi staged through smem
// TRANSPOSED with coalesced loads; thread=(r, 4 d's) -> no reduction needed.
// Dynamic smem: xs[1024] cs[2048] sn[2048] wr[32*132] wi[32*132] = 54272 B.
// ---------------------------------------------------------------------------
__global__ __launch_bounds__(256)
void layers_kernel(const float* __restrict__ W,
                   const float* __restrict__ bvec,
                   const float* __restrict__ Wr,
                   const float* __restrict__ Wi)
{
    extern __shared__ float sm[];
    float* xs = sm;              // [8][128]
    float* cs = sm + 1024;       // [8][256]
    float* sn = sm + 3072;       // [8][256]
    float* wr = sm + 5120;       // [32][132] transposed tile
    float* wi = sm + 5120 + 32*132;

    int tid = threadIdx.x;
    int g0  = blockIdx.x * 8;
    float tphi = __fmul_rn((float)(g0 >> 3), PHI_F);  // all 8 rows share t

    for (int idx = tid; idx < 8*128; idx += 256)
        xs[idx] = g_X[g0*128 + idx];
    __syncthreads();

    int rB = tid >> 5;           // phase-B row (one warp per r)
    int dg = (tid & 31) * 4;     // phase-B d-group

    for (int l = 0; l < L_; ++l) {
        // ---- phase A: th = x @ W.T + b + t_phi ; table lookup ----
        {
            int n = tid;
            const float4* w4p = (const float4*)(W + ((size_t)l*N_ + n)*D_);
            float acc[8];
#pragma unroll
            for (int r = 0; r < 8; ++r) acc[r] = 0.f;
#pragma unroll 8
            for (int d4 = 0; d4 < 32; ++d4) {
                float4 w4 = __ldg(&w4p[d4]);
#pragma unroll
                for (int r = 0; r < 8; ++r) {
                    float4 x4 = *(const float4*)&xs[r*128 + d4*4];
                    acc[r] += x4.x*w4.x + x4.y*w4.y + x4.z*w4.z + x4.w*w4.w;
                }
            }
            float bv = bvec[l*N_ + n];
#pragma unroll
            for (int r = 0; r < 8; ++r) {
                float th = __fadd_rn(__fadd_rn(acc[r], bv), tphi);
                int idx = theta_idx(th);
                cs[r*256 + n] = __ldg(&g_cos[idx]);
                sn[r*256 + n] = __ldg(&g_sin[idx]);
            }
        }
        __syncthreads();

        // ---- phase B: o = cs @ Wr.T + sn @ Wi.T, tiled over n ----
        float acc[4] = {0.f, 0.f, 0.f, 0.f};
        for (int nt = 0; nt < 8; ++nt) {
            int n0 = nt * 32;
            // stage transposed tiles (coalesced float4 global reads)
#pragma unroll
            for (int k = 0; k < 4; ++k) {
                int idx = tid + k*256;
                int row = idx >> 3, c4 = (idx & 7) * 4;
                float4 a = __ldg((const float4*)(Wr + ((size_t)l*D_ + row)*N_ + n0 + c4));
                float4 b = __ldg((const float4*)(Wi + ((size_t)l*D_ + row)*N_ + n0 + c4));
                wr[(c4+0)*132 + row] = a.x; wr[(c4+1)*132 + row] = a.y;
                wr[(c4+2)*132 + row] = a.z; wr[(c4+3)*132 + row] = a.w;
                wi[(c4+0)*132 + row] = b.x; wi[(c4+1)*132 + row] = b.y;
                wi[(c4+2)*132 + row] = b.z; wi[(c4+3)*132 + row] = b.w;
            }
            __syncthreads();
#pragma unroll 8
            for (int c = 0; c < 32; ++c) {
                float cv = cs[rB*256 + n0 + c];   // broadcast
                float sv = sn[rB*256 + n0 + c];
                float4 w4 = *(const float4*)&wr[c*132 + dg];
                float4 v4 = *(const float4*)&wi[c*132 + dg];
                acc[0] += cv*w4.x + sv*v4.x;
                acc[1] += cv*w4.y + sv*v4.y;
                acc[2] += cv*w4.z + sv*v4.z;
                acc[3] += cv*w4.w + sv*v4.w;
            }
            __syncthreads();
        }
        // silu update — thread owns xs[rB][dg..dg+3]
#pragma unroll
        for (int j = 0; j < 4; ++j) {
            float o  = acc[j];
            float sg = 1.0f / (1.0f + expf(-o));
            xs[rB*128 + dg + j] += o * sg;
        }
        __syncthreads();
    }

    for (int idx = tid; idx < 8*128; idx += 256)
        g_X[g0*128 + idx] = xs[idx];
}

// ---------------------------------------------------------------------------
// K3: logits GEMM, tf32 mma.sync.m16n8k8 with ldmatrix fragment loads and
// register double-buffering. BM=128, BN=256, BK=32, 512 threads (16 warps,
// 2m x 8n, warp tile 64x32).
// ---------------------------------------------------------------------------
#define BM 128
#define BN 256
#define BK 32
#define SKA 36
#define GEMM_SMEM_WORDS (2*BM*SKA + 2*BN*SKA)   // 27648 words = 110592 B

__global__ __launch_bounds__(512)
void gemm_kernel(const float* __restrict__ Wv, float* __restrict__ out)
{
    extern __shared__ unsigned gsm[];
    int tid  = threadIdx.x;
    int lane = tid & 31, warp = tid >> 5;
    int wm = warp >> 3, wn = warp & 7;
    int m0 = blockIdx.x * BM;
    int v0 = blockIdx.y * BN;

    unsigned smem_base = (unsigned)__cvta_generic_to_shared(gsm);

    float c[4][4][4];
#pragma unroll
    for (int mt = 0; mt < 4; ++mt)
#pragma unroll
        for (int nt = 0; nt < 4; ++nt)
#pragma unroll
            for (int i = 0; i < 4; ++i) c[mt][nt][i] = 0.f;

    float4 areg[2], breg[4];

    auto load_g = [&](int kc) {
#pragma unroll
        for (int l = 0; l < 2; ++l) {
            int idx = tid + l*512, row = idx >> 3, c4 = (idx & 7) * 4;
            areg[l] = *(const float4*)(g_X + (size_t)(m0 + row)*D_ + kc*BK + c4);
        }
#pragma unroll
        for (int l = 0; l < 4; ++l) {
            int idx = tid + l*512, row = idx >> 3, c4 = (idx & 7) * 4;
            int gr = v0 + row;
            breg[l] = (gr < V_)
                ? *(const float4*)(Wv + (size_t)gr*D_ + kc*BK + c4)
                : make_float4(0.f, 0.f, 0.f, 0.f);
        }
    };
    auto store_s = [&](int buf) {
        unsigned* A  = gsm + buf*(BM*SKA);
        unsigned* Bb = gsm + 2*BM*SKA + buf*(BN*SKA);
#pragma unroll
        for (int l = 0; l < 2; ++l) {
            int idx = tid + l*512, row = idx >> 3, c4 = (idx & 7) * 4;
            A[row*SKA+c4+0] = f2tf(areg[l].x); A[row*SKA+c4+1] = f2tf(areg[l].y);
            A[row*SKA+c4+2] = f2tf(areg[l].z); A[row*SKA+c4+3] = f2tf(areg[l].w);
        }
#pragma unroll
        for (int l = 0; l < 4; ++l) {
            int idx = tid + l*512, row = idx >> 3, c4 = (idx & 7) * 4;
            Bb[row*SKA+c4+0] = f2tf(breg[l].x); Bb[row*SKA+c4+1] = f2tf(breg[l].y);
            Bb[row*SKA+c4+2] = f2tf(breg[l].z); Bb[row*SKA+c4+3] = f2tf(breg[l].w);
        }
    };

    load_g(0);
    store_s(0);
    __syncthreads();

    // ldmatrix per-thread row/col offsets
    int a_r = wm*64 + (lane & 7) + ((lane >> 3) & 1) * 8;
    int a_c = (lane >> 4) * 4;
    int b_r = wn*32 + (lane & 7);
    int b_c = ((lane >> 3) & 1) * 4;

    for (int kc = 0; kc < 4; ++kc) {
        if (kc < 3) load_g(kc + 1);
        int buf = kc & 1;
        unsigned abase = smem_base + (unsigned)(buf*(BM*SKA)) * 4u;
        unsigned bbase = smem_base + (unsigned)(2*BM*SKA + buf*(BN*SKA)) * 4u;

#pragma unroll
        for (int kk = 0; kk < 4; ++kk) {
            unsigned af[4][4], bf[4][2];
#pragma unroll
            for (int mt = 0; mt < 4; ++mt) {
                unsigned addr = abase + (unsigned)((a_r + mt*16)*SKA + kk*8 + a_c) * 4u;
                asm volatile("ldmatrix.sync.aligned.m8n8.x4.shared.b16 {%0,%1,%2,%3}, [%4];"
                    : "=r"(af[mt][0]), "=r"(af[mt][1]), "=r"(af[mt][2]), "=r"(af[mt][3])
                    : "r"(addr));
            }
#pragma unroll
            for (int nt = 0; nt < 4; ++nt) {
                unsigned addr = bbase + (unsigned)((b_r + nt*8)*SKA + kk*8 + b_c) * 4u;
                asm volatile("ldmatrix.sync.aligned.m8n8.x2.shared.b16 {%0,%1}, [%2];"
                    : "=r"(bf[nt][0]), "=r"(bf[nt][1])
                    : "r"(addr));
            }
#pragma unroll
            for (int mt = 0; mt < 4; ++mt)
#pragma unroll
                for (int nt = 0; nt < 4; ++nt) {
                    asm volatile(
                        "mma.sync.aligned.m16n8k8.row.col.f32.tf32.tf32.f32 "
                        "{%0,%1,%2,%3},{%4,%5,%6,%7},{%8,%9},{%0,%1,%2,%3};"
                        : "+f"(c[mt][nt][0]), "+f"(c[mt][nt][1]),
                          "+f"(c[mt][nt][2]), "+f"(c[mt][nt][3])
                        : "r"(af[mt][0]), "r"(af[mt][1]),
                          "r"(af[mt][2]), "r"(af[mt][3]),
                          "r"(bf[nt][0]), "r"(bf[nt][1]));
                }
        }
        if (kc < 3) {
            __syncthreads();
            store_s(buf ^ 1);
            __syncthreads();
        }
    }

    // epilogue: row R -> (b = R&7, t = R>>3), out layout (B,S,V)
#pragma unroll
    for (int mt = 0; mt < 4; ++mt) {
        int R0 = m0 + wm*64 + mt*16 + (lane >> 2);
        int R1 = R0 + 8;
        size_t base0 = ((size_t)((R0 & 7)*S_ + (R0 >> 3))) * V_;
        size_t base1 = ((size_t)((R1 & 7)*S_ + (R1 >> 3))) * V_;
#pragma unroll
        for (int nt = 0; nt < 4; ++nt) {
            int col = v0 + wn*32 + nt*8 + (lane & 3)*2;
            if (col < V_) {
                out[base0 + col] = c[mt][nt][0];
                out[base1 + col] = c[mt][nt][2];
            }
            if (col + 1 < V_) {
                out[base0 + col + 1] = c[mt][nt][1];
                out[base1 + col + 1] = c[mt][nt][3];
            }
        }
    }
}

// ---------------------------------------------------------------------------
extern "C" void kernel_launch(void* const* d_in, const int* in_sizes, int n_in,
                              void* d_out, int out_size)
{
    const int*   ids = (const int*)  d_in[0];
    const float* emb = (const float*)d_in[1];
    const float* W   = (const float*)d_in[2];
    const float* bv  = (const float*)d_in[3];
    const float* Wr  = (const float*)d_in[4];
    const float* Wi  = (const float*)d_in[5];
    const float* ow  = (const float*)d_in[6];
    float* out = (float*)d_out;

    cudaFuncSetAttribute(layers_kernel,
        cudaFuncAttributeMaxDynamicSharedMemorySize, 54272);
    cudaFuncSetAttribute(gemm_kernel,
        cudaFuncAttributeMaxDynamicSharedMemorySize, GEMM_SMEM_WORDS * 4);

    tab_kernel<<<16, 256>>>();
    scan_kernel<<<B_, D_>>>(ids, emb, out);
    layers_kernel<<<M_/8, 256, 54272>>>(W, bv, Wr, Wi);
    dim3 grid(M_ / BM, (V_ + BN - 1) / BN);   // (16, 197), x fastest
    gemm_kernel<<<grid, 512, GEMM_SMEM_WORDS * 4>>>(ow, out);
}